// round 17
// baseline (speedup 1.0000x reference)
#include <cuda_runtime.h>
#include <cuda_bf16.h>

#define VOCAB 50000
#define D 256
#define E 20000
#define L 20

// ---------------- scratch (static device globals; no allocation) ----------------
__device__ float g_qemb[D];
__device__ float g_g0[D];
__device__ float g_g1[D];
__device__ float g_u[VOCAB];
__device__ float g_w[VOCAB];
__device__ __align__(16) float g_A[VOCAB];
__device__ __align__(16) float g_B[VOCAB];
__device__ float g_accA[D];
__device__ float g_accB[D];
__device__ float g_wte1[D];
__device__ float g_sumw;
__device__ float g_sumexp;

__device__ __forceinline__ float warp_sum(float v) {
    #pragma unroll
    for (int o = 16; o > 0; o >>= 1) v += __shfl_xor_sync(0xffffffffu, v, o);
    return v;
}

__device__ __forceinline__ float dot8(float4 x0, float4 x1, float4 c0, float4 c1) {
    return x0.x*c0.x + x0.y*c0.y + x0.z*c0.z + x0.w*c0.w
         + x1.x*c1.x + x1.y*c1.y + x1.z*c1.z + x1.w*c1.w;
}

// ---- bulk-TMA + mbarrier helpers (CUTLASS-exact instruction forms) --------------
__device__ __forceinline__ unsigned smem_u32(const void* p) {
    return (unsigned)__cvta_generic_to_shared(p);
}
__device__ __forceinline__ void mbar_init(unsigned mbar, unsigned cnt) {
    asm volatile("mbarrier.init.shared::cta.b64 [%0], %1;" :: "r"(mbar), "r"(cnt) : "memory");
}
__device__ __forceinline__ void mbar_expect_tx(unsigned mbar, unsigned bytes) {
    asm volatile("mbarrier.arrive.expect_tx.shared::cta.b64 _, [%0], %1;"
                 :: "r"(mbar), "r"(bytes) : "memory");
}
__device__ __forceinline__ void tma_bulk_g2s(unsigned sdst, const void* gsrc,
                                             unsigned bytes, unsigned mbar) {
    asm volatile("cp.async.bulk.shared::cluster.global.mbarrier::complete_tx::bytes "
                 "[%0], [%1], %2, [%3];"
                 :: "r"(sdst), "l"(gsrc), "r"(bytes), "r"(mbar) : "memory");
}
__device__ __forceinline__ void mbar_wait(unsigned mbar, unsigned parity) {
    asm volatile("{\n\t"
                 ".reg .pred P;\n\t"
                 "WAIT%=:\n\t"
                 "mbarrier.try_wait.parity.shared::cta.b64 P, [%0], %1;\n\t"
                 "@!P bra WAIT%=;\n\t"
                 "}" :: "r"(mbar), "r"(parity) : "memory");
}

#define TGRID   888                  // exactly 6 CTAs/SM (888 = 6*148)
#define TCR     8                    // rows per chunk (8KB)
#define TCB     (TCR * D * 4)        // bytes per chunk
#define TNCH    (VOCAB / TCR)        // 6250 chunks
#define NST     4                    // pipeline stages (32KB smem)

// ---------------- K1: q_emb + derived vectors, zero accumulators ----------------
__global__ void k1_qemb(const int* __restrict__ question,
                        const float* __restrict__ q_table) {
    int d = threadIdx.x;                         // 256 threads
    float a  = 1.0f - (float)d * (1.0f / D);
    float be = 2.0f * (float)d * (1.0f / D) - 1.0f;
    float s = 0.0f;
    #pragma unroll
    for (int l = 0; l < L; ++l) {
        int v = question[l];
        float pe = a + ((float)l * (1.0f / L)) * be;
        s += __ldg(&q_table[(size_t)v * D + d]) * pe;
    }
    g_qemb[d] = s;
    g_g0[d] = a * s;
    g_g1[d] = be * s;
    g_accA[d] = 0.0f; g_accB[d] = 0.0f; g_wte1[d] = 0.0f;
    if (d == 0) { g_sumw = 0.0f; g_sumexp = 0.0f; }
}

// ---------------- K2: u[v], w[v] over q_table via bulk-TMA; zero A/B -------------
// 1 row per warp per chunk (8 rows/chunk).
__global__ void __launch_bounds__(256, 6)
k2_uw(const float* __restrict__ q_table) {
    __shared__ __align__(128) float buf[NST][TCR * D];
    __shared__ __align__(8) unsigned long long mbar_s[NST];
    __shared__ float4 s0[64], s1[64];
    int t = threadIdx.x;                      // 256
    int warp = t >> 5, lane = t & 31;
    unsigned mbv[NST];
    #pragma unroll
    for (int s = 0; s < NST; ++s) mbv[s] = smem_u32(&mbar_s[s]);
    if (t == 0) {
        #pragma unroll
        for (int s = 0; s < NST; ++s) mbar_init(mbv[s], 1);
    }
    if (t < 64) {
        s0[t] = ((const float4*)g_g0)[t];
        s1[t] = ((const float4*)g_g1)[t];
    }
    __syncthreads();
    if (t == 0) {
        #pragma unroll
        for (int s = 0; s < NST - 1; ++s) {
            int c = blockIdx.x + s * TGRID;
            if (c < TNCH) {
                mbar_expect_tx(mbv[s], TCB);
                tma_bulk_g2s(smem_u32(buf[s]), q_table + (size_t)c * TCR * D, TCB, mbv[s]);
            }
        }
    }
    float4 c0 = s0[lane], c1 = s0[lane + 32];
    float4 d0 = s1[lane], d1 = s1[lane + 32];
    int i = 0;
    for (int c = blockIdx.x; c < TNCH; c += TGRID, ++i) {
        int stage = i & (NST - 1);
        int parity = (i / NST) & 1;
        mbar_wait(mbv[stage], parity);
        const float4* bf = (const float4*)buf[stage];
        float4 x0 = bf[warp * 64 + lane];
        float4 x1 = bf[warp * 64 + lane + 32];
        __syncthreads();                      // reads complete -> refill early
        if (t == 0) {
            int cn = c + (NST - 1) * TGRID;
            int fs = (stage + NST - 1) & (NST - 1);
            if (cn < TNCH) {
                mbar_expect_tx(mbv[fs], TCB);
                tma_bulk_g2s(smem_u32(buf[fs]), q_table + (size_t)cn * TCR * D, TCB, mbv[fs]);
            }
        }
        float u = dot8(x0, x1, c0, c1);
        float w = dot8(x0, x1, d0, d1);
        u = warp_sum(u); w = warp_sum(w);
        int v = c * TCR + warp;
        if (lane == 0) { g_u[v] = u; g_w[v] = w; }
        if (t < TCR) { g_A[c * TCR + t] = 0.0f; g_B[c * TCR + t] = 0.0f; }
    }
}

// ---------------- K34: fused scores + exp + A/B scatter + weights@te1 ------------
#define K34_CHUNK  32
#define K34_BLOCKS (E / K34_CHUNK)    // 625
__global__ void k34_weights(const int* __restrict__ evidence,
                            const float* __restrict__ te2,
                            const float* __restrict__ te1) {
    __shared__ float4 sq[64];
    __shared__ float s_w[K34_CHUNK];
    int t = threadIdx.x;                      // 256
    int warp = t >> 5, lane = t & 31;
    if (t < 64) sq[t] = ((const float4*)g_qemb)[t];
    __syncthreads();
    int e0 = blockIdx.x * K34_CHUNK;
    float4 q0 = sq[lane], q1 = sq[lane + 32];
    float part[4];
    #pragma unroll
    for (int r = 0; r < 4; ++r) {
        int e = e0 + warp * 4 + r;
        float p = 0.0f;
        if (lane < L) {
            int v = __ldg(&evidence[e * L + lane]);
            p = g_u[v] + ((float)lane * (1.0f / L)) * g_w[v];
        }
        const float4* row = (const float4*)(te2 + (size_t)e * D);
        float4 x0 = __ldg(&row[lane]);
        float4 x1 = __ldg(&row[lane + 32]);
        part[r] = p + dot8(x0, x1, q0, q1);
    }
    #pragma unroll
    for (int r = 0; r < 4; ++r) part[r] = warp_sum(part[r]);
    if (lane == 0) {
        #pragma unroll
        for (int r = 0; r < 4; ++r) s_w[warp * 4 + r] = part[r];
    }
    __syncthreads();
    if (t < 32) {
        float w = expf(s_w[t]);
        s_w[t] = w;
        float s = warp_sum(w);
        if (t == 0) atomicAdd(&g_sumw, s);
    }
    __syncthreads();
    for (int i = t; i < K34_CHUNK * L; i += 256) {
        int el = i / L;
        int l  = i - el * L;
        int v  = __ldg(&evidence[(e0 + el) * L + l]);
        float w = s_w[el];
        atomicAdd(&g_A[v], w);
        atomicAdd(&g_B[v], w * ((float)l * (1.0f / L)));
    }
    int d = t;
    float acc = 0.0f;
    #pragma unroll 8
    for (int el = 0; el < K34_CHUNK; ++el)
        acc += s_w[el] * __ldg(&te1[(size_t)(e0 + el) * D + d]);
    atomicAdd(&g_wte1[d], acc);
}

// ---------------- K5: accA/accB = A@e_table, B@e_table (bulk-TMA, 4 stages) ------
__global__ void __launch_bounds__(256, 6)
k5_etable(const float* __restrict__ e_table) {
    __shared__ __align__(128) float buf[NST][TCR * D];
    __shared__ __align__(8) unsigned long long mbar_s[NST];
    int t = threadIdx.x;                      // 256 (= column)
    unsigned mbv[NST];
    #pragma unroll
    for (int s = 0; s < NST; ++s) mbv[s] = smem_u32(&mbar_s[s]);
    if (t == 0) {
        #pragma unroll
        for (int s = 0; s < NST; ++s) mbar_init(mbv[s], 1);
    }
    __syncthreads();
    if (t == 0) {
        #pragma unroll
        for (int s = 0; s < NST - 1; ++s) {
            int c = blockIdx.x + s * TGRID;
            if (c < TNCH) {
                mbar_expect_tx(mbv[s], TCB);
                tma_bulk_g2s(smem_u32(buf[s]), e_table + (size_t)c * TCR * D, TCB, mbv[s]);
            }
        }
    }
    float a = 0.0f, b = 0.0f;
    int i = 0;
    for (int c = blockIdx.x; c < TNCH; c += TGRID, ++i) {
        int stage = i & (NST - 1);
        int parity = (i / NST) & 1;
        int v0 = c * TCR;
        float4 A0 = __ldg((const float4*)&g_A[v0]);
        float4 A1 = __ldg((const float4*)&g_A[v0 + 4]);
        float4 B0 = __ldg((const float4*)&g_B[v0]);
        float4 B1 = __ldg((const float4*)&g_B[v0 + 4]);
        mbar_wait(mbv[stage], parity);
        const float* base = buf[stage] + t;
        float x0 = base[0 * D], x1 = base[1 * D], x2 = base[2 * D], x3 = base[3 * D];
        float x4 = base[4 * D], x5 = base[5 * D], x6 = base[6 * D], x7 = base[7 * D];
        __syncthreads();                      // reads complete -> refill early
        if (t == 0) {
            int cn = c + (NST - 1) * TGRID;
            int fs = (stage + NST - 1) & (NST - 1);
            if (cn < TNCH) {
                mbar_expect_tx(mbv[fs], TCB);
                tma_bulk_g2s(smem_u32(buf[fs]), e_table + (size_t)cn * TCR * D, TCB, mbv[fs]);
            }
        }
        a += A0.x*x0 + A0.y*x1 + A0.z*x2 + A0.w*x3
           + A1.x*x4 + A1.y*x5 + A1.z*x6 + A1.w*x7;
        b += B0.x*x0 + B0.y*x1 + B0.z*x2 + B0.w*x3
           + B1.x*x4 + B1.y*x5 + B1.z*x6 + B1.w*x7;
    }
    atomicAdd(&g_accA[t], a);
    atomicAdd(&g_accB[t], b);
}

// ---------------- K6: logits + exp + sumexp (bulk-TMA over W, 4 stages) ----------
// 1 row per warp per chunk.
__global__ void __launch_bounds__(256, 6)
k6_logits(const float* __restrict__ W, const float* __restrict__ bb,
          float* __restrict__ out) {
    __shared__ __align__(128) float buf[NST][TCR * D];
    __shared__ __align__(8) unsigned long long mbar_s[NST];
    __shared__ float s_feat[D];
    __shared__ float s_p[8];
    int t = threadIdx.x;                      // 256
    int warp = t >> 5, lane = t & 31;
    unsigned mbv[NST];
    #pragma unroll
    for (int s = 0; s < NST; ++s) mbv[s] = smem_u32(&mbar_s[s]);
    if (t == 0) {
        #pragma unroll
        for (int s = 0; s < NST; ++s) mbar_init(mbv[s], 1);
    }
    {
        float a  = 1.0f - (float)t * (1.0f / D);
        float be = 2.0f * (float)t * (1.0f / D) - 1.0f;
        float invS = 1.0f / g_sumw;
        s_feat[t] = (a * g_accA[t] + be * g_accB[t] + g_wte1[t]) * invS + g_qemb[t];
    }
    __syncthreads();
    if (t == 0) {
        #pragma unroll
        for (int s = 0; s < NST - 1; ++s) {
            int c = blockIdx.x + s * TGRID;
            if (c < TNCH) {
                mbar_expect_tx(mbv[s], TCB);
                tma_bulk_g2s(smem_u32(buf[s]), W + (size_t)c * TCR * D, TCB, mbv[s]);
            }
        }
    }
    const float4* sf = (const float4*)s_feat;
    float4 f0 = sf[lane], f1 = sf[lane + 32];
    float p_sum = 0.0f;
    int i = 0;
    for (int c = blockIdx.x; c < TNCH; c += TGRID, ++i) {
        int stage = i & (NST - 1);
        int parity = (i / NST) & 1;
        int v = c * TCR + warp;
        float bias = __ldg(&bb[v]);
        mbar_wait(mbv[stage], parity);
        const float4* bf = (const float4*)buf[stage];
        float4 x0 = bf[warp * 64 + lane];
        float4 x1 = bf[warp * 64 + lane + 32];
        __syncthreads();                      // reads complete -> refill early
        if (t == 0) {
            int cn = c + (NST - 1) * TGRID;
            int fs = (stage + NST - 1) & (NST - 1);
            if (cn < TNCH) {
                mbar_expect_tx(mbv[fs], TCB);
                tma_bulk_g2s(smem_u32(buf[fs]), W + (size_t)cn * TCR * D, TCB, mbv[fs]);
            }
        }
        float s = dot8(x0, x1, f0, f1);
        s = warp_sum(s);
        if (lane == 0) {
            float p = expf(s + bias);
            out[v] = p;                       // unnormalized
            p_sum += p;
        }
    }
    if (lane == 0) s_p[warp] = p_sum;
    __syncthreads();
    if (t < 8) {
        float x = s_p[t];
        #pragma unroll
        for (int o = 4; o > 0; o >>= 1) x += __shfl_xor_sync(0xffu, x, o);
        if (t == 0) atomicAdd(&g_sumexp, x);
    }
}

// ---------------- K7: normalize output (float4) ----------------------------------
__global__ void k7_scale(float* __restrict__ out) {
    int i = blockIdx.x * blockDim.x + threadIdx.x;   // VOCAB/4 = 12500 float4
    float inv = 1.0f / g_sumexp;
    if (i < VOCAB / 4) {
        float4 v = ((const float4*)out)[i];
        v.x *= inv; v.y *= inv; v.z *= inv; v.w *= inv;
        ((float4*)out)[i] = v;
    }
}

// ---------------- launch ---------------------------------------------------------
extern "C" void kernel_launch(void* const* d_in, const int* in_sizes, int n_in,
                              void* d_out, int out_size) {
    const int*   evidence = (const int*)  d_in[0];
    const int*   question = (const int*)  d_in[1];
    const float* q_table  = (const float*)d_in[2];
    const float* e_table  = (const float*)d_in[3];
    const float* te1      = (const float*)d_in[4];
    const float* te2      = (const float*)d_in[5];
    const float* W        = (const float*)d_in[6];
    const float* b        = (const float*)d_in[7];
    float* out = (float*)d_out;

    k1_qemb<<<1, 256>>>(question, q_table);
    k2_uw<<<TGRID, 256>>>(q_table);
    k34_weights<<<K34_BLOCKS, 256>>>(evidence, te2, te1);
    k5_etable<<<TGRID, 256>>>(e_table);
    k6_logits<<<TGRID, 256>>>(W, b, out);
    k7_scale<<<(VOCAB / 4 + 255) / 256, 256>>>(out);
}